// round 14
// baseline (speedup 1.0000x reference)
#include <cuda_runtime.h>
#include <cuda_bf16.h>
#include <cstdint>
#include <cstddef>

// ----------------------------------------------------------------------------
//   x[T,D] -> enc = x @ enc_w^T + enc_b            (T=4096, D=1024, P=512)
//   enc_n, pat_n = L2-normalized rows (eps 1e-8)
//   sim = enc_n @ pat_n^T                          [T, N]  N=65536
//   idx = top-128(sim); mean_pat = mean(patterns[idx])
//   out = x + alpha * (mean_pat @ dec_w^T + dec_b)
//
// All GEMMs HMMA bf16x3 (AhBh + AhBl + AlBh, fp32 accum), R9 mainloop
// (issue cp(c+1) -> CP_WAIT(1) -> barrier -> compute -> barrier) — FROZEN,
// empirically fastest (R10/R11 restructures regressed).
// sim writes + topk reads use streaming cache policy (.cs) so Bh/Bl and
// patterns stay L2-resident. topk prefilter uses warp-aggregated atomics.
// ----------------------------------------------------------------------------

#define T_TOK 4096
#define D_DIM 1024
#define P_DIM 512
#define N_PAT 65536
#define K_TOP 128

// Static scratch (no runtime allocation).
__device__ float         g_enc [(size_t)T_TOK * P_DIM];
__device__ __nv_bfloat16 g_Ah  [(size_t)T_TOK * P_DIM];
__device__ __nv_bfloat16 g_Al  [(size_t)T_TOK * P_DIM];
__device__ __nv_bfloat16 g_Bh  [(size_t)N_PAT * P_DIM];
__device__ __nv_bfloat16 g_Bl  [(size_t)N_PAT * P_DIM];
__device__ __nv_bfloat16 g_xh [(size_t)T_TOK * D_DIM];
__device__ __nv_bfloat16 g_xl [(size_t)T_TOK * D_DIM];
__device__ __nv_bfloat16 g_ewh[(size_t)P_DIM * D_DIM];
__device__ __nv_bfloat16 g_ewl[(size_t)P_DIM * D_DIM];
__device__ __nv_bfloat16 g_dwh[(size_t)D_DIM * P_DIM];
__device__ __nv_bfloat16 g_dwl[(size_t)D_DIM * P_DIM];
__device__ float         g_sim [(size_t)T_TOK * N_PAT];   // 1 GiB
__device__ int           g_topk[(size_t)T_TOK * K_TOP];
__device__ float         g_p0  [(size_t)T_TOK * P_DIM];
__device__ float         g_p1  [(size_t)T_TOK * P_DIM];
__device__ __nv_bfloat16 g_mh  [(size_t)T_TOK * P_DIM];
__device__ __nv_bfloat16 g_ml  [(size_t)T_TOK * P_DIM];

// ============================================================================
// PTX helpers — all compute_80-level (safe for compute_103 without 'a')
// ============================================================================
__device__ __forceinline__ uint32_t smem_to_u32(const void* p) {
    uint32_t a;
    asm("{ .reg .u64 t; cvta.to.shared.u64 t, %1; cvt.u32.u64 %0, t; }"
        : "=r"(a) : "l"(p));
    return a;
}

__device__ __forceinline__ void ldsm4(uint32_t& r0, uint32_t& r1,
                                      uint32_t& r2, uint32_t& r3, uint32_t a) {
    asm volatile("ldmatrix.sync.aligned.m8n8.x4.shared.b16 {%0,%1,%2,%3}, [%4];"
                 : "=r"(r0), "=r"(r1), "=r"(r2), "=r"(r3) : "r"(a));
}

__device__ __forceinline__ void mma16816(float* c,
                                         const uint32_t* a,
                                         const uint32_t* b) {
    asm volatile(
        "mma.sync.aligned.m16n8k16.row.col.f32.bf16.bf16.f32 "
        "{%0,%1,%2,%3}, {%4,%5,%6,%7}, {%8,%9}, {%0,%1,%2,%3};"
        : "+f"(c[0]), "+f"(c[1]), "+f"(c[2]), "+f"(c[3])
        : "r"(a[0]), "r"(a[1]), "r"(a[2]), "r"(a[3]), "r"(b[0]), "r"(b[1]));
}

#define CP_ASYNC16(dst_u32, src_ptr) \
    asm volatile("cp.async.cg.shared.global [%0], [%1], 16;" \
                 :: "r"(dst_u32), "l"(src_ptr))
#define CP_COMMIT() asm volatile("cp.async.commit_group;" ::: "memory")
#define CP_WAIT(n)  asm volatile("cp.async.wait_group %0;" :: "n"(n) : "memory")

__device__ __forceinline__ unsigned f2ord(float f) {
    unsigned x = __float_as_uint(f);
    return x ^ ((x & 0x80000000u) ? 0xFFFFFFFFu : 0x80000000u);
}

// streaming (evict-first) 8B store: sim is write-once/read-once, keep L2 for B
__device__ __forceinline__ void stcs_f2(float* p, float a, float b) {
    asm volatile("st.global.cs.v2.f32 [%0], {%1, %2};"
                 :: "l"(p), "f"(a), "f"(b) : "memory");
}

// ============================================================================
// Shared tile-copy for all HMMA GEMMs (4 tensors, double buffer).
// SMEM chunk: [128 rows x 32 k] bf16; 16B chunk (row,c16) at row*80 + c16*16.
// ============================================================================
#define SIM_TILE_B   10240
#define SIM_BUF_B    40960
#define SIM_SMEM_B   81920

__device__ __forceinline__ void hmma_cp_chunk(
    uint32_t sbase,
    const __nv_bfloat16* __restrict__ Ah, const __nv_bfloat16* __restrict__ Al,
    const __nv_bfloat16* __restrict__ Bh, const __nv_bfloat16* __restrict__ Bl,
    int m0, int n0, int c, int buf, int tid, int kdim)
{
    const int kofs = c * 32;
    const uint32_t dbase = sbase + (uint32_t)buf * SIM_BUF_B;
#pragma unroll
    for (int t = 0; t < 4; t++) {
        const __nv_bfloat16* src = (t == 0) ? Ah : (t == 1) ? Al : (t == 2) ? Bh : Bl;
        const int rbase = (t < 2) ? m0 : n0;
#pragma unroll
        for (int i = 0; i < 2; i++) {
            int lin = i * 256 + tid;      // 512 chunks of 16B per tile
            int row = lin >> 2;           // 0..127
            int c16 = lin & 3;            // 0..3
            const void* g = src + (size_t)(rbase + row) * kdim + kofs + c16 * 8;
            uint32_t d = dbase + (uint32_t)t * SIM_TILE_B
                       + (uint32_t)(row * 80 + c16 * 16);
            CP_ASYNC16(d, g);
        }
    }
    CP_COMMIT();
}

// ============================================================================
// Shared mainloop body (compute one 32-wide K-chunk from SMEM buf).
// ============================================================================
__device__ __forceinline__ void hmma_compute_chunk(
    uint32_t bufbase, int lane, int warp_m, int warp_n, float acc[2][8][4])
{
    const uint32_t ab  = bufbase;
    const uint32_t alb = bufbase + SIM_TILE_B;
    const uint32_t bhb = bufbase + 2 * SIM_TILE_B;
    const uint32_t blb = bufbase + 3 * SIM_TILE_B;

#pragma unroll
    for (int ks = 0; ks < 2; ks++) {
        uint32_t fah[2][4], fal[2][4];
        {
            const int arow = warp_m * 32 + (lane & 15);
            const int ac16 = ks * 2 + (lane >> 4);
#pragma unroll
            for (int mi = 0; mi < 2; mi++) {
                uint32_t off = (uint32_t)((arow + mi * 16) * 80 + ac16 * 16);
                ldsm4(fah[mi][0], fah[mi][1], fah[mi][2], fah[mi][3], ab + off);
                ldsm4(fal[mi][0], fal[mi][1], fal[mi][2], fal[mi][3], alb + off);
            }
        }
        uint32_t fbh[8][2], fbl[8][2];
        {
            const int g = lane >> 3;
            const int brow = warp_n * 64 + (g >> 1) * 8 + (lane & 7);
            const int bc16 = ks * 2 + (g & 1);
#pragma unroll
            for (int np = 0; np < 4; np++) {
                uint32_t off = (uint32_t)((brow + np * 16) * 80 + bc16 * 16);
                uint32_t r0, r1, r2, r3;
                ldsm4(r0, r1, r2, r3, bhb + off);
                fbh[np * 2][0] = r0; fbh[np * 2][1] = r1;
                fbh[np * 2 + 1][0] = r2; fbh[np * 2 + 1][1] = r3;
                ldsm4(r0, r1, r2, r3, blb + off);
                fbl[np * 2][0] = r0; fbl[np * 2][1] = r1;
                fbl[np * 2 + 1][0] = r2; fbl[np * 2 + 1][1] = r3;
            }
        }
#pragma unroll
        for (int mi = 0; mi < 2; mi++)
#pragma unroll
            for (int ni = 0; ni < 8; ni++) {
                mma16816(acc[mi][ni], fah[mi], fbh[ni]);
                mma16816(acc[mi][ni], fah[mi], fbl[ni]);
                mma16816(acc[mi][ni], fal[mi], fbh[ni]);
            }
    }
}

// ============================================================================
// sim GEMM — R9 structure (FROZEN): issue cp(c+1) -> CP_WAIT(1) -> barrier ->
// compute(c) -> barrier.  Epilogue stores with .cs (streaming).
// ============================================================================
__global__ __launch_bounds__(256)
void sim_mma_kernel(const __nv_bfloat16* __restrict__ Ah,
                    const __nv_bfloat16* __restrict__ Al,
                    const __nv_bfloat16* __restrict__ Bh,
                    const __nv_bfloat16* __restrict__ Bl,
                    float* __restrict__ sim)
{
    extern __shared__ char smem[];
    const uint32_t sbase = smem_to_u32(smem);
    const int tid = threadIdx.x;
    const int wid = tid >> 5;
    const int lane = tid & 31;
    const int m0 = blockIdx.x * 128;   // x fastest over M -> B tile shared in wave
    const int n0 = blockIdx.y * 128;
    const int warp_m = wid >> 1;
    const int warp_n = wid & 1;

    float acc[2][8][4];
#pragma unroll
    for (int mi = 0; mi < 2; mi++)
#pragma unroll
        for (int ni = 0; ni < 8; ni++)
#pragma unroll
            for (int q = 0; q < 4; q++) acc[mi][ni][q] = 0.0f;

    hmma_cp_chunk(sbase, Ah, Al, Bh, Bl, m0, n0, 0, 0, tid, P_DIM);

    for (int c = 0; c < 16; c++) {
        if (c + 1 < 16) {
            hmma_cp_chunk(sbase, Ah, Al, Bh, Bl, m0, n0, c + 1, (c + 1) & 1,
                          tid, P_DIM);
            CP_WAIT(1);
        } else {
            CP_WAIT(0);
        }
        __syncthreads();
        hmma_compute_chunk(sbase + (uint32_t)(c & 1) * SIM_BUF_B,
                           lane, warp_m, warp_n, acc);
        __syncthreads();
    }

    const int row = m0 + warp_m * 32 + (lane >> 2);
    const int colb = n0 + warp_n * 64 + (lane & 3) * 2;
#pragma unroll
    for (int mi = 0; mi < 2; mi++)
#pragma unroll
        for (int ni = 0; ni < 8; ni++) {
            stcs_f2(&sim[(size_t)(row + mi * 16) * N_PAT + colb + ni * 8],
                    acc[mi][ni][0], acc[mi][ni][1]);
            stcs_f2(&sim[(size_t)(row + mi * 16 + 8) * N_PAT + colb + ni * 8],
                    acc[mi][ni][2], acc[mi][ni][3]);
        }
}

// ============================================================================
// Generic HMMA GEMM for enc/dec — same R9 loop structure.
// EPI 1: C = acc + bias[n];  EPI 2: C = resid + alpha[0]*(acc + bias[n])
// ============================================================================
template <int EPI, int KCHUNKS, int NOUT, int KDIM>
__global__ __launch_bounds__(256)
void hmma_gemm_kernel(const __nv_bfloat16* __restrict__ Ah,
                      const __nv_bfloat16* __restrict__ Al,
                      const __nv_bfloat16* __restrict__ Bh,
                      const __nv_bfloat16* __restrict__ Bl,
                      const float* __restrict__ bias,
                      float* __restrict__ C,
                      const float* __restrict__ resid,
                      const float* __restrict__ alpha)
{
    extern __shared__ char smem[];
    const uint32_t sbase = smem_to_u32(smem);
    const int tid = threadIdx.x;
    const int wid = tid >> 5;
    const int lane = tid & 31;
    const int m0 = blockIdx.x * 128;
    const int n0 = blockIdx.y * 128;
    const int warp_m = wid >> 1;
    const int warp_n = wid & 1;

    float acc[2][8][4];
#pragma unroll
    for (int mi = 0; mi < 2; mi++)
#pragma unroll
        for (int ni = 0; ni < 8; ni++)
#pragma unroll
            for (int q = 0; q < 4; q++) acc[mi][ni][q] = 0.0f;

    hmma_cp_chunk(sbase, Ah, Al, Bh, Bl, m0, n0, 0, 0, tid, KDIM);

    for (int c = 0; c < KCHUNKS; c++) {
        if (c + 1 < KCHUNKS) {
            hmma_cp_chunk(sbase, Ah, Al, Bh, Bl, m0, n0, c + 1, (c + 1) & 1,
                          tid, KDIM);
            CP_WAIT(1);
        } else {
            CP_WAIT(0);
        }
        __syncthreads();
        hmma_compute_chunk(sbase + (uint32_t)(c & 1) * SIM_BUF_B,
                           lane, warp_m, warp_n, acc);
        __syncthreads();
    }

    const float a_val = (EPI == 2) ? alpha[0] : 0.0f;
    const int row = m0 + warp_m * 32 + (lane >> 2);
    const int colb = n0 + warp_n * 64 + (lane & 3) * 2;
#pragma unroll
    for (int mi = 0; mi < 2; mi++)
#pragma unroll
        for (int ni = 0; ni < 8; ni++) {
            const int c0 = colb + ni * 8;
            const float b0 = bias[c0], b1 = bias[c0 + 1];
#pragma unroll
            for (int rr = 0; rr < 2; rr++) {
                const int r = row + mi * 16 + rr * 8;
                const size_t off = (size_t)r * NOUT + c0;
                float v0 = acc[mi][ni][rr * 2 + 0] + b0;
                float v1 = acc[mi][ni][rr * 2 + 1] + b1;
                if (EPI == 2) {
                    v0 = resid[off] + a_val * v0;
                    v1 = resid[off + 1] + a_val * v1;
                }
                *reinterpret_cast<float2*>(&C[off]) = make_float2(v0, v1);
            }
        }
}

// ============================================================================
// fp32 -> bf16 high/low split (elementwise)
// ============================================================================
__global__ __launch_bounds__(256)
void split_kernel(const float* __restrict__ in,
                  __nv_bfloat16* __restrict__ h, __nv_bfloat16* __restrict__ l,
                  int n)
{
    int i = blockIdx.x * 256 + threadIdx.x;
    if (i < n) {
        float v = in[i];
        __nv_bfloat16 hh = __float2bfloat16(v);
        h[i] = hh;
        l[i] = __float2bfloat16(v - __bfloat162float(hh));
    }
}

// ============================================================================
// Fused row L2-normalize + bf16x2 split (cols = 512, 256 threads/row).
// ============================================================================
__global__ __launch_bounds__(256)
void rownorm_split_kernel(const float* __restrict__ in,
                          __nv_bfloat16* __restrict__ oh,
                          __nv_bfloat16* __restrict__ ol)
{
    const int r = blockIdx.x;
    const int tid = threadIdx.x;
    const float* row = in + (size_t)r * P_DIM;
    float v0 = row[tid], v1 = row[tid + 256];
    float ss = fmaf(v0, v0, v1 * v1);
#pragma unroll
    for (int o = 16; o > 0; o >>= 1) ss += __shfl_xor_sync(0xFFFFFFFFu, ss, o);
    __shared__ float wsum[8];
    if ((tid & 31) == 0) wsum[tid >> 5] = ss;
    __syncthreads();
    if (tid < 32) {
        float v = (tid < 8) ? wsum[tid] : 0.0f;
#pragma unroll
        for (int o = 4; o > 0; o >>= 1) v += __shfl_xor_sync(0xFFFFFFFFu, v, o);
        if (tid == 0) wsum[0] = v;
    }
    __syncthreads();
    const float inv = 1.0f / fmaxf(sqrtf(wsum[0]), 1e-8f);

    float n0 = v0 * inv, n1 = v1 * inv;
    __nv_bfloat16 h0 = __float2bfloat16(n0);
    __nv_bfloat16 h1 = __float2bfloat16(n1);
    __nv_bfloat16 l0 = __float2bfloat16(n0 - __bfloat162float(h0));
    __nv_bfloat16 l1 = __float2bfloat16(n1 - __bfloat162float(h1));
    oh[(size_t)r * P_DIM + tid] = h0;
    oh[(size_t)r * P_DIM + tid + 256] = h1;
    ol[(size_t)r * P_DIM + tid] = l0;
    ol[(size_t)r * P_DIM + tid + 256] = l1;
}

// ============================================================================
// Exact top-128 per token (1-pass >=2sigma prefilter + exact fallback).
// Streaming loads (.cs); warp-aggregated candidate append; output SORTED.
// ============================================================================
#define TK_CAP 4096
#define TK_EQ  64

__device__ __forceinline__ void warp_append(bool hit, unsigned u, int idx,
                                            int* s_cnt,
                                            unsigned* ukey, int* uidx)
{
    unsigned m = __ballot_sync(0xFFFFFFFFu, hit);
    if (m == 0u) return;
    const int lane = threadIdx.x & 31;
    const int leader = __ffs(m) - 1;
    int base = 0;
    if (lane == leader) base = atomicAdd(s_cnt, __popc(m));
    base = __shfl_sync(0xFFFFFFFFu, base, leader);
    if (hit) {
        int p = base + __popc(m & ((1u << lane) - 1u));
        if (p < TK_CAP) { ukey[p] = u; uidx[p] = idx; }
    }
}

__global__ __launch_bounds__(256)
void topk_kernel(const float* __restrict__ sim, int* __restrict__ topk)
{
    const int t = blockIdx.x;
    const int tid = threadIdx.x;
    const float* row = sim + (size_t)t * N_PAT;

    __shared__ unsigned ukey[TK_CAP];   // fallback aliases this as hist[4096]
    __shared__ int      uidx[TK_CAP];
    __shared__ unsigned h2[256];
    __shared__ unsigned s_prefix;
    __shared__ int s_want, s_out, s_ce, s_cnt, s_b, s_cg;
    __shared__ int eqidx[TK_EQ];
    __shared__ int outsel[K_TOP];

    const unsigned TAU0 = f2ord(0.0883883476f);   // 2/sqrt(512)

    if (tid == 0) s_cnt = 0;
    __syncthreads();

#pragma unroll 2
    for (int i = 0; i < N_PAT / 1024; i++) {
        const int idx = (i * 256 + tid) * 4;
        float4 v = __ldcs(reinterpret_cast<const float4*>(&row[idx]));
        unsigned u0 = f2ord(v.x), u1 = f2ord(v.y);
        unsigned u2 = f2ord(v.z), u3 = f2ord(v.w);
        warp_append(u0 >= TAU0, u0, idx,     &s_cnt, ukey, uidx);
        warp_append(u1 >= TAU0, u1, idx + 1, &s_cnt, ukey, uidx);
        warp_append(u2 >= TAU0, u2, idx + 2, &s_cnt, ukey, uidx);
        warp_append(u3 >= TAU0, u3, idx + 3, &s_cnt, ukey, uidx);
    }
    __syncthreads();

    int cnt;
    if (s_cnt >= K_TOP && s_cnt <= TK_CAP) {
        cnt = s_cnt;
    } else {
        // fallback: full-row 2-pass scan (exact)
        unsigned* hist = ukey;
        for (int i = tid; i < TK_CAP; i += 256) hist[i] = 0u;
        __syncthreads();
#pragma unroll 4
        for (int i = 0; i < N_PAT / 256; i++) {
            unsigned u = f2ord(row[i * 256 + tid]);
            atomicAdd(&hist[u >> 20], 1u);
        }
        __syncthreads();
        const int base = 4095 - tid * 16;
        unsigned lsum = 0;
#pragma unroll
        for (int j = 0; j < 16; j++) lsum += hist[base - j];
        h2[tid] = lsum;
        __syncthreads();
        if (tid == 0) {
            unsigned run = 0;
            for (int i = 0; i < 256; i++) { unsigned c = h2[i]; h2[i] = run; run += c; }
        }
        __syncthreads();
        {
            unsigned run = h2[tid];
            if (run < (unsigned)K_TOP && run + lsum >= (unsigned)K_TOP) {
                unsigned r = run;
#pragma unroll
                for (int j = 0; j < 16; j++) {
                    unsigned c = hist[base - j];
                    if (r + c >= (unsigned)K_TOP) { s_b = base - j; s_cg = (int)r; break; }
                    r += c;
                }
            }
        }
        if (tid == 0) s_cnt = 0;
        __syncthreads();
        const unsigned floorkey = ((unsigned)s_b) << 20;
        __syncthreads();
#pragma unroll 4
        for (int i = 0; i < N_PAT / 256; i++) {
            const int idx = i * 256 + tid;
            unsigned u = f2ord(row[idx]);
            if (u >= floorkey) {
                int p = atomicAdd(&s_cnt, 1);
                if (p < 2048) { ukey[p] = u; uidx[p] = idx; }
            }
        }
        __syncthreads();
        cnt = min(s_cnt, 2048);
    }

    // exact full-key radix select
    if (tid == 0) { s_prefix = 0u; s_want = K_TOP; }
    __syncthreads();

#pragma unroll
    for (int p = 0; p < 4; p++) {
        const int sh = 24 - 8 * p;
        h2[tid] = 0u;
        __syncthreads();
        const unsigned mask_hi = (p == 0) ? 0u : ~((0x1u << (sh + 8)) - 1u);
        const unsigned pfx = s_prefix;
        for (int i = tid; i < cnt; i += 256) {
            unsigned u = ukey[i];
            if ((u & mask_hi) == pfx)
                atomicAdd(&h2[(u >> sh) & 255u], 1u);
        }
        __syncthreads();
        if (tid == 0) {
            unsigned run = 0;
            int want = s_want;
            for (int bin = 255; bin >= 0; bin--) {
                unsigned c = h2[bin];
                if (run + c >= (unsigned)want) {
                    s_prefix = pfx | ((unsigned)bin << sh);
                    s_want = want - (int)run;
                    break;
                }
                run += c;
            }
        }
        __syncthreads();
    }

    const unsigned tau = s_prefix;
    const int want_eq = s_want;

    if (tid == 0) { s_out = 0; s_ce = 0; }
    __syncthreads();

    for (int i = tid; i < cnt; i += 256) {
        unsigned u = ukey[i];
        if (u > tau) {
            int p = atomicAdd(&s_out, 1);
            if (p < K_TOP) outsel[p] = uidx[i];
        } else if (u == tau) {
            int p = atomicAdd(&s_ce, 1);
            if (p < TK_EQ) eqidx[p] = uidx[i];
        }
    }
    __syncthreads();

    if (tid == 0) {
        const int cg = min(s_out, K_TOP);
        int ce = min(s_ce, TK_EQ);
        int need = min(want_eq, ce);
        for (int s = 0; s < need; s++) {
            int best = s;
            for (int q = s + 1; q < ce; q++)
                if (eqidx[q] < eqidx[best]) best = q;
            int tmp = eqidx[s]; eqidx[s] = eqidx[best]; eqidx[best] = tmp;
            outsel[cg + s] = eqidx[s];
        }
    }
    __syncthreads();

    for (int k = 2; k <= K_TOP; k <<= 1) {
        for (int j = k >> 1; j > 0; j >>= 1) {
            if (tid < K_TOP) {
                int ixj = tid ^ j;
                if (ixj > tid) {
                    int a = outsel[tid], b = outsel[ixj];
                    bool asc = ((tid & k) == 0);
                    if (asc ? (a > b) : (a < b)) { outsel[tid] = b; outsel[ixj] = a; }
                }
            }
            __syncthreads();
        }
    }
    if (tid < K_TOP) topk[(size_t)t * K_TOP + tid] = outsel[tid];
}

// ============================================================================
// Gather halves (sorted indices -> deterministic) + combine into bf16 split.
// ============================================================================
__global__ __launch_bounds__(256)
void gather_half_kernel(const float* __restrict__ patterns,
                        const int* __restrict__ topk,
                        float* __restrict__ p0, float* __restrict__ p1)
{
    const int b = blockIdx.x;
    const int t = b >> 1;
    const int half = b & 1;
    const int tid = threadIdx.x;

    __shared__ int sidx[64];
    if (tid < 64) sidx[tid] = topk[(size_t)t * K_TOP + half * 64 + tid];
    __syncthreads();

    float a0 = 0.0f, a1 = 0.0f;
#pragma unroll 4
    for (int k = 0; k < 64; k++) {
        const float* prow = patterns + (size_t)sidx[k] * P_DIM;
        a0 += prow[tid];
        a1 += prow[tid + 256];
    }
    float* dst = (half ? p1 : p0) + (size_t)t * P_DIM;
    dst[tid] = a0;
    dst[tid + 256] = a1;
}

__global__ __launch_bounds__(256)
void combine_split_kernel(const float* __restrict__ p0,
                          const float* __restrict__ p1,
                          __nv_bfloat16* __restrict__ mh,
                          __nv_bfloat16* __restrict__ ml, int n)
{
    int i = blockIdx.x * 256 + threadIdx.x;
    if (i < n) {
        float v = (p0[i] + p1[i]) * (1.0f / K_TOP);
        __nv_bfloat16 hh = __float2bfloat16(v);
        mh[i] = hh;
        ml[i] = __float2bfloat16(v - __bfloat162float(hh));
    }
}

// ============================================================================
// Launch
// ============================================================================
extern "C" void kernel_launch(void* const* d_in, const int* in_sizes, int n_in,
                              void* d_out, int out_size)
{
    const float* x        = (const float*)d_in[0];
    const float* patterns = (const float*)d_in[1];
    const float* alpha    = (const float*)d_in[2];
    const float* enc_w    = (const float*)d_in[3];
    const float* enc_b    = (const float*)d_in[4];
    const float* dec_w    = (const float*)d_in[5];
    const float* dec_b    = (const float*)d_in[6];
    float* out = (float*)d_out;

    float *enc, *sim, *p0, *p1;
    __nv_bfloat16 *Ah, *Al, *Bh, *Bl, *xh, *xl, *ewh, *ewl, *dwh, *dwl, *mh, *ml;
    int* topk;
    cudaGetSymbolAddress((void**)&enc,  g_enc);
    cudaGetSymbolAddress((void**)&Ah,   g_Ah);
    cudaGetSymbolAddress((void**)&Al,   g_Al);
    cudaGetSymbolAddress((void**)&Bh,   g_Bh);
    cudaGetSymbolAddress((void**)&Bl,   g_Bl);
    cudaGetSymbolAddress((void**)&xh,   g_xh);
    cudaGetSymbolAddress((void**)&xl,   g_xl);
    cudaGetSymbolAddress((void**)&ewh,  g_ewh);
    cudaGetSymbolAddress((void**)&ewl,  g_ewl);
    cudaGetSymbolAddress((void**)&dwh,  g_dwh);
    cudaGetSymbolAddress((void**)&dwl,  g_dwl);
    cudaGetSymbolAddress((void**)&sim,  g_sim);
    cudaGetSymbolAddress((void**)&topk, g_topk);
    cudaGetSymbolAddress((void**)&p0,   g_p0);
    cudaGetSymbolAddress((void**)&p1,   g_p1);
    cudaGetSymbolAddress((void**)&mh,   g_mh);
    cudaGetSymbolAddress((void**)&ml,   g_ml);

    cudaFuncSetAttribute(sim_mma_kernel,
                         cudaFuncAttributeMaxDynamicSharedMemorySize, SIM_SMEM_B);
    cudaFuncSetAttribute((const void*)hmma_gemm_kernel<1, 32, 512, 1024>,
                         cudaFuncAttributeMaxDynamicSharedMemorySize, SIM_SMEM_B);
    cudaFuncSetAttribute((const void*)hmma_gemm_kernel<2, 16, 1024, 512>,
                         cudaFuncAttributeMaxDynamicSharedMemorySize, SIM_SMEM_B);

    // 0) bf16 splits of x, enc_w, dec_w
    split_kernel<<<(T_TOK * D_DIM + 255) / 256, 256>>>(x, xh, xl, T_TOK * D_DIM);
    split_kernel<<<(P_DIM * D_DIM + 255) / 256, 256>>>(enc_w, ewh, ewl, P_DIM * D_DIM);
    split_kernel<<<(D_DIM * P_DIM + 255) / 256, 256>>>(dec_w, dwh, dwl, D_DIM * P_DIM);

    // 1) encoder GEMM (HMMA)
    {
        dim3 grid(T_TOK / 128, P_DIM / 128);
        hmma_gemm_kernel<1, 32, 512, 1024><<<grid, 256, SIM_SMEM_B>>>(
            xh, xl, ewh, ewl, enc_b, enc, nullptr, nullptr);
    }
    // 2) normalize + bf16x2 split
    rownorm_split_kernel<<<T_TOK, 256>>>(enc, Ah, Al);
    rownorm_split_kernel<<<N_PAT, 256>>>(patterns, Bh, Bl);
    // 3) sim GEMM (HMMA bf16x3, R9 mainloop, .cs stores)
    {
        dim3 grid(T_TOK / 128, N_PAT / 128);
        sim_mma_kernel<<<grid, 256, SIM_SMEM_B>>>(Ah, Al, Bh, Bl, sim);
    }
    // 4) exact top-128 (sorted output)
    topk_kernel<<<T_TOK, 256>>>(sim, topk);
    // 5) gather halves + combine into bf16-split mean
    gather_half_kernel<<<T_TOK * 2, 256>>>(patterns, topk, p0, p1);
    combine_split_kernel<<<(T_TOK * P_DIM + 255) / 256, 256>>>(p0, p1, mh, ml,
                                                               T_TOK * P_DIM);
    // 6) decoder GEMM + residual (HMMA)
    {
        dim3 grid(T_TOK / 128, D_DIM / 128);
        hmma_gemm_kernel<2, 16, 1024, 512><<<grid, 256, SIM_SMEM_B>>>(
            mh, ml, dwh, dwl, dec_b, out, x, alpha);
    }
}

// round 15
// speedup vs baseline: 1.0498x; 1.0498x over previous
#include <cuda_runtime.h>
#include <cuda_bf16.h>
#include <cstdint>
#include <cstddef>

// ----------------------------------------------------------------------------
//   x[T,D] -> enc = x @ enc_w^T + enc_b            (T=4096, D=1024, P=512)
//   enc_n, pat_n = L2-normalized rows (eps 1e-8)
//   sim = enc_n @ pat_n^T                          [T, N]  N=65536
//   idx = top-128(sim); mean_pat = mean(patterns[idx])
//   out = x + alpha * (mean_pat @ dec_w^T + dec_b)
//
// R9 configuration restored (best known: 2734 us). All GEMMs HMMA bf16x3
// (AhBh + AhBl + AlBh, fp32 accum) with the R9 mainloop:
//   issue cp(c+1) -> CP_WAIT(1) -> barrier -> compute(c) -> barrier
// FROZEN: R10 (A-direct), R11 (single-barrier), R13 (.cs/warp-agg) all
// regressed. topk: 1-pass >=2sigma prefilter + exact fallback, sorted out.
// gather: 2-way split + combine. Only change vs R9: the three fp32->bf16
// split launches are merged into one segmented launch (identical math).
// ----------------------------------------------------------------------------

#define T_TOK 4096
#define D_DIM 1024
#define P_DIM 512
#define N_PAT 65536
#define K_TOP 128

// Static scratch (no runtime allocation).
__device__ float         g_enc [(size_t)T_TOK * P_DIM];
__device__ __nv_bfloat16 g_Ah  [(size_t)T_TOK * P_DIM];
__device__ __nv_bfloat16 g_Al  [(size_t)T_TOK * P_DIM];
__device__ __nv_bfloat16 g_Bh  [(size_t)N_PAT * P_DIM];
__device__ __nv_bfloat16 g_Bl  [(size_t)N_PAT * P_DIM];
__device__ __nv_bfloat16 g_xh [(size_t)T_TOK * D_DIM];
__device__ __nv_bfloat16 g_xl [(size_t)T_TOK * D_DIM];
__device__ __nv_bfloat16 g_ewh[(size_t)P_DIM * D_DIM];
__device__ __nv_bfloat16 g_ewl[(size_t)P_DIM * D_DIM];
__device__ __nv_bfloat16 g_dwh[(size_t)D_DIM * P_DIM];
__device__ __nv_bfloat16 g_dwl[(size_t)D_DIM * P_DIM];
__device__ float         g_sim [(size_t)T_TOK * N_PAT];   // 1 GiB
__device__ int           g_topk[(size_t)T_TOK * K_TOP];
__device__ float         g_p0  [(size_t)T_TOK * P_DIM];
__device__ float         g_p1  [(size_t)T_TOK * P_DIM];
__device__ __nv_bfloat16 g_mh  [(size_t)T_TOK * P_DIM];
__device__ __nv_bfloat16 g_ml  [(size_t)T_TOK * P_DIM];

// ============================================================================
// PTX helpers — all compute_80-level (safe for compute_103 without 'a')
// ============================================================================
__device__ __forceinline__ uint32_t smem_to_u32(const void* p) {
    uint32_t a;
    asm("{ .reg .u64 t; cvta.to.shared.u64 t, %1; cvt.u32.u64 %0, t; }"
        : "=r"(a) : "l"(p));
    return a;
}

__device__ __forceinline__ void ldsm4(uint32_t& r0, uint32_t& r1,
                                      uint32_t& r2, uint32_t& r3, uint32_t a) {
    asm volatile("ldmatrix.sync.aligned.m8n8.x4.shared.b16 {%0,%1,%2,%3}, [%4];"
                 : "=r"(r0), "=r"(r1), "=r"(r2), "=r"(r3) : "r"(a));
}

__device__ __forceinline__ void mma16816(float* c,
                                         const uint32_t* a,
                                         const uint32_t* b) {
    asm volatile(
        "mma.sync.aligned.m16n8k16.row.col.f32.bf16.bf16.f32 "
        "{%0,%1,%2,%3}, {%4,%5,%6,%7}, {%8,%9}, {%0,%1,%2,%3};"
        : "+f"(c[0]), "+f"(c[1]), "+f"(c[2]), "+f"(c[3])
        : "r"(a[0]), "r"(a[1]), "r"(a[2]), "r"(a[3]), "r"(b[0]), "r"(b[1]));
}

#define CP_ASYNC16(dst_u32, src_ptr) \
    asm volatile("cp.async.cg.shared.global [%0], [%1], 16;" \
                 :: "r"(dst_u32), "l"(src_ptr))
#define CP_COMMIT() asm volatile("cp.async.commit_group;" ::: "memory")
#define CP_WAIT(n)  asm volatile("cp.async.wait_group %0;" :: "n"(n) : "memory")

__device__ __forceinline__ unsigned f2ord(float f) {
    unsigned x = __float_as_uint(f);
    return x ^ ((x & 0x80000000u) ? 0xFFFFFFFFu : 0x80000000u);
}

// ============================================================================
// Shared tile-copy for all HMMA GEMMs (4 tensors, double buffer).
// SMEM chunk: [128 rows x 32 k] bf16; 16B chunk (row,c16) at row*80 + c16*16.
// ============================================================================
#define SIM_TILE_B   10240
#define SIM_BUF_B    40960
#define SIM_SMEM_B   81920

__device__ __forceinline__ void hmma_cp_chunk(
    uint32_t sbase,
    const __nv_bfloat16* __restrict__ Ah, const __nv_bfloat16* __restrict__ Al,
    const __nv_bfloat16* __restrict__ Bh, const __nv_bfloat16* __restrict__ Bl,
    int m0, int n0, int c, int buf, int tid, int kdim)
{
    const int kofs = c * 32;
    const uint32_t dbase = sbase + (uint32_t)buf * SIM_BUF_B;
#pragma unroll
    for (int t = 0; t < 4; t++) {
        const __nv_bfloat16* src = (t == 0) ? Ah : (t == 1) ? Al : (t == 2) ? Bh : Bl;
        const int rbase = (t < 2) ? m0 : n0;
#pragma unroll
        for (int i = 0; i < 2; i++) {
            int lin = i * 256 + tid;      // 512 chunks of 16B per tile
            int row = lin >> 2;           // 0..127
            int c16 = lin & 3;            // 0..3
            const void* g = src + (size_t)(rbase + row) * kdim + kofs + c16 * 8;
            uint32_t d = dbase + (uint32_t)t * SIM_TILE_B
                       + (uint32_t)(row * 80 + c16 * 16);
            CP_ASYNC16(d, g);
        }
    }
    CP_COMMIT();
}

// ============================================================================
// Shared mainloop body (compute one 32-wide K-chunk from SMEM buf).
// ============================================================================
__device__ __forceinline__ void hmma_compute_chunk(
    uint32_t bufbase, int lane, int warp_m, int warp_n, float acc[2][8][4])
{
    const uint32_t ab  = bufbase;
    const uint32_t alb = bufbase + SIM_TILE_B;
    const uint32_t bhb = bufbase + 2 * SIM_TILE_B;
    const uint32_t blb = bufbase + 3 * SIM_TILE_B;

#pragma unroll
    for (int ks = 0; ks < 2; ks++) {
        uint32_t fah[2][4], fal[2][4];
        {
            const int arow = warp_m * 32 + (lane & 15);
            const int ac16 = ks * 2 + (lane >> 4);
#pragma unroll
            for (int mi = 0; mi < 2; mi++) {
                uint32_t off = (uint32_t)((arow + mi * 16) * 80 + ac16 * 16);
                ldsm4(fah[mi][0], fah[mi][1], fah[mi][2], fah[mi][3], ab + off);
                ldsm4(fal[mi][0], fal[mi][1], fal[mi][2], fal[mi][3], alb + off);
            }
        }
        uint32_t fbh[8][2], fbl[8][2];
        {
            const int g = lane >> 3;
            const int brow = warp_n * 64 + (g >> 1) * 8 + (lane & 7);
            const int bc16 = ks * 2 + (g & 1);
#pragma unroll
            for (int np = 0; np < 4; np++) {
                uint32_t off = (uint32_t)((brow + np * 16) * 80 + bc16 * 16);
                uint32_t r0, r1, r2, r3;
                ldsm4(r0, r1, r2, r3, bhb + off);
                fbh[np * 2][0] = r0; fbh[np * 2][1] = r1;
                fbh[np * 2 + 1][0] = r2; fbh[np * 2 + 1][1] = r3;
                ldsm4(r0, r1, r2, r3, blb + off);
                fbl[np * 2][0] = r0; fbl[np * 2][1] = r1;
                fbl[np * 2 + 1][0] = r2; fbl[np * 2 + 1][1] = r3;
            }
        }
#pragma unroll
        for (int mi = 0; mi < 2; mi++)
#pragma unroll
            for (int ni = 0; ni < 8; ni++) {
                mma16816(acc[mi][ni], fah[mi], fbh[ni]);
                mma16816(acc[mi][ni], fah[mi], fbl[ni]);
                mma16816(acc[mi][ni], fal[mi], fbh[ni]);
            }
    }
}

// ============================================================================
// sim GEMM — R9 structure (FROZEN): issue cp(c+1) -> CP_WAIT(1) -> barrier ->
// compute(c) -> barrier.
// ============================================================================
__global__ __launch_bounds__(256)
void sim_mma_kernel(const __nv_bfloat16* __restrict__ Ah,
                    const __nv_bfloat16* __restrict__ Al,
                    const __nv_bfloat16* __restrict__ Bh,
                    const __nv_bfloat16* __restrict__ Bl,
                    float* __restrict__ sim)
{
    extern __shared__ char smem[];
    const uint32_t sbase = smem_to_u32(smem);
    const int tid = threadIdx.x;
    const int wid = tid >> 5;
    const int lane = tid & 31;
    const int m0 = blockIdx.x * 128;   // x fastest over M -> B tile shared in wave
    const int n0 = blockIdx.y * 128;
    const int warp_m = wid >> 1;
    const int warp_n = wid & 1;

    float acc[2][8][4];
#pragma unroll
    for (int mi = 0; mi < 2; mi++)
#pragma unroll
        for (int ni = 0; ni < 8; ni++)
#pragma unroll
            for (int q = 0; q < 4; q++) acc[mi][ni][q] = 0.0f;

    hmma_cp_chunk(sbase, Ah, Al, Bh, Bl, m0, n0, 0, 0, tid, P_DIM);

    for (int c = 0; c < 16; c++) {
        if (c + 1 < 16) {
            hmma_cp_chunk(sbase, Ah, Al, Bh, Bl, m0, n0, c + 1, (c + 1) & 1,
                          tid, P_DIM);
            CP_WAIT(1);
        } else {
            CP_WAIT(0);
        }
        __syncthreads();
        hmma_compute_chunk(sbase + (uint32_t)(c & 1) * SIM_BUF_B,
                           lane, warp_m, warp_n, acc);
        __syncthreads();
    }

    const int row = m0 + warp_m * 32 + (lane >> 2);
    const int colb = n0 + warp_n * 64 + (lane & 3) * 2;
#pragma unroll
    for (int mi = 0; mi < 2; mi++)
#pragma unroll
        for (int ni = 0; ni < 8; ni++) {
            float2 v01 = make_float2(acc[mi][ni][0], acc[mi][ni][1]);
            float2 v23 = make_float2(acc[mi][ni][2], acc[mi][ni][3]);
            *reinterpret_cast<float2*>(
                &sim[(size_t)(row + mi * 16) * N_PAT + colb + ni * 8]) = v01;
            *reinterpret_cast<float2*>(
                &sim[(size_t)(row + mi * 16 + 8) * N_PAT + colb + ni * 8]) = v23;
        }
}

// ============================================================================
// Generic HMMA GEMM for enc/dec — same R9 loop structure.
// EPI 1: C = acc + bias[n];  EPI 2: C = resid + alpha[0]*(acc + bias[n])
// ============================================================================
template <int EPI, int KCHUNKS, int NOUT, int KDIM>
__global__ __launch_bounds__(256)
void hmma_gemm_kernel(const __nv_bfloat16* __restrict__ Ah,
                      const __nv_bfloat16* __restrict__ Al,
                      const __nv_bfloat16* __restrict__ Bh,
                      const __nv_bfloat16* __restrict__ Bl,
                      const float* __restrict__ bias,
                      float* __restrict__ C,
                      const float* __restrict__ resid,
                      const float* __restrict__ alpha)
{
    extern __shared__ char smem[];
    const uint32_t sbase = smem_to_u32(smem);
    const int tid = threadIdx.x;
    const int wid = tid >> 5;
    const int lane = tid & 31;
    const int m0 = blockIdx.x * 128;
    const int n0 = blockIdx.y * 128;
    const int warp_m = wid >> 1;
    const int warp_n = wid & 1;

    float acc[2][8][4];
#pragma unroll
    for (int mi = 0; mi < 2; mi++)
#pragma unroll
        for (int ni = 0; ni < 8; ni++)
#pragma unroll
            for (int q = 0; q < 4; q++) acc[mi][ni][q] = 0.0f;

    hmma_cp_chunk(sbase, Ah, Al, Bh, Bl, m0, n0, 0, 0, tid, KDIM);

    for (int c = 0; c < KCHUNKS; c++) {
        if (c + 1 < KCHUNKS) {
            hmma_cp_chunk(sbase, Ah, Al, Bh, Bl, m0, n0, c + 1, (c + 1) & 1,
                          tid, KDIM);
            CP_WAIT(1);
        } else {
            CP_WAIT(0);
        }
        __syncthreads();
        hmma_compute_chunk(sbase + (uint32_t)(c & 1) * SIM_BUF_B,
                           lane, warp_m, warp_n, acc);
        __syncthreads();
    }

    const float a_val = (EPI == 2) ? alpha[0] : 0.0f;
    const int row = m0 + warp_m * 32 + (lane >> 2);
    const int colb = n0 + warp_n * 64 + (lane & 3) * 2;
#pragma unroll
    for (int mi = 0; mi < 2; mi++)
#pragma unroll
        for (int ni = 0; ni < 8; ni++) {
            const int c0 = colb + ni * 8;
            const float b0 = bias[c0], b1 = bias[c0 + 1];
#pragma unroll
            for (int rr = 0; rr < 2; rr++) {
                const int r = row + mi * 16 + rr * 8;
                const size_t off = (size_t)r * NOUT + c0;
                float v0 = acc[mi][ni][rr * 2 + 0] + b0;
                float v1 = acc[mi][ni][rr * 2 + 1] + b1;
                if (EPI == 2) {
                    v0 = resid[off] + a_val * v0;
                    v1 = resid[off + 1] + a_val * v1;
                }
                *reinterpret_cast<float2*>(&C[off]) = make_float2(v0, v1);
            }
        }
}

// ============================================================================
// fp32 -> bf16 high/low split, three segments in ONE launch (identical math
// to three separate split launches; segment resolved per element index).
// seg0: x [0, n0); seg1: enc_w [n0, n0+n1); seg2: dec_w [n0+n1, n0+n1+n2)
// ============================================================================
__global__ __launch_bounds__(256)
void split3_kernel(const float* __restrict__ s0, __nv_bfloat16* __restrict__ h0,
                   __nv_bfloat16* __restrict__ l0, int n0,
                   const float* __restrict__ s1, __nv_bfloat16* __restrict__ h1,
                   __nv_bfloat16* __restrict__ l1, int n1,
                   const float* __restrict__ s2, __nv_bfloat16* __restrict__ h2,
                   __nv_bfloat16* __restrict__ l2, int n2)
{
    int i = blockIdx.x * 256 + threadIdx.x;
    const float* src;
    __nv_bfloat16 *dh, *dl;
    int j;
    if (i < n0)           { src = s0; dh = h0; dl = l0; j = i; }
    else if (i < n0 + n1) { src = s1; dh = h1; dl = l1; j = i - n0; }
    else if (i < n0 + n1 + n2) { src = s2; dh = h2; dl = l2; j = i - n0 - n1; }
    else return;
    float v = src[j];
    __nv_bfloat16 hh = __float2bfloat16(v);
    dh[j] = hh;
    dl[j] = __float2bfloat16(v - __bfloat162float(hh));
}

// ============================================================================
// Fused row L2-normalize + bf16x2 split (cols = 512, 256 threads/row).
// ============================================================================
__global__ __launch_bounds__(256)
void rownorm_split_kernel(const float* __restrict__ in,
                          __nv_bfloat16* __restrict__ oh,
                          __nv_bfloat16* __restrict__ ol)
{
    const int r = blockIdx.x;
    const int tid = threadIdx.x;
    const float* row = in + (size_t)r * P_DIM;
    float v0 = row[tid], v1 = row[tid + 256];
    float ss = fmaf(v0, v0, v1 * v1);
#pragma unroll
    for (int o = 16; o > 0; o >>= 1) ss += __shfl_xor_sync(0xFFFFFFFFu, ss, o);
    __shared__ float wsum[8];
    if ((tid & 31) == 0) wsum[tid >> 5] = ss;
    __syncthreads();
    if (tid < 32) {
        float v = (tid < 8) ? wsum[tid] : 0.0f;
#pragma unroll
        for (int o = 4; o > 0; o >>= 1) v += __shfl_xor_sync(0xFFFFFFFFu, v, o);
        if (tid == 0) wsum[0] = v;
    }
    __syncthreads();
    const float inv = 1.0f / fmaxf(sqrtf(wsum[0]), 1e-8f);

    float n0 = v0 * inv, n1 = v1 * inv;
    __nv_bfloat16 h0 = __float2bfloat16(n0);
    __nv_bfloat16 h1 = __float2bfloat16(n1);
    __nv_bfloat16 l0 = __float2bfloat16(n0 - __bfloat162float(h0));
    __nv_bfloat16 l1 = __float2bfloat16(n1 - __bfloat162float(h1));
    oh[(size_t)r * P_DIM + tid] = h0;
    oh[(size_t)r * P_DIM + tid + 256] = h1;
    ol[(size_t)r * P_DIM + tid] = l0;
    ol[(size_t)r * P_DIM + tid + 256] = l1;
}

// ============================================================================
// Exact top-128 per token (1-pass >=2sigma prefilter + exact fallback).
// Output indices bitonic-SORTED ascending -> deterministic downstream.
// (R9 version: plain atomics, plain loads.)
// ============================================================================
#define TK_CAP 4096
#define TK_EQ  64

__global__ __launch_bounds__(256)
void topk_kernel(const float* __restrict__ sim, int* __restrict__ topk)
{
    const int t = blockIdx.x;
    const int tid = threadIdx.x;
    const float* row = sim + (size_t)t * N_PAT;

    __shared__ unsigned ukey[TK_CAP];   // fallback aliases this as hist[4096]
    __shared__ int      uidx[TK_CAP];
    __shared__ unsigned h2[256];
    __shared__ unsigned s_prefix;
    __shared__ int s_want, s_out, s_ce, s_cnt, s_b, s_cg;
    __shared__ int eqidx[TK_EQ];
    __shared__ int outsel[K_TOP];

    const unsigned TAU0 = f2ord(0.0883883476f);   // 2/sqrt(512)

    if (tid == 0) s_cnt = 0;
    __syncthreads();

#pragma unroll 2
    for (int i = 0; i < N_PAT / 1024; i++) {
        const int idx = (i * 256 + tid) * 4;
        float4 v = *reinterpret_cast<const float4*>(&row[idx]);
        unsigned u0 = f2ord(v.x), u1 = f2ord(v.y);
        unsigned u2 = f2ord(v.z), u3 = f2ord(v.w);
        if (u0 >= TAU0) {
            int p = atomicAdd(&s_cnt, 1);
            if (p < TK_CAP) { ukey[p] = u0; uidx[p] = idx; }
        }
        if (u1 >= TAU0) {
            int p = atomicAdd(&s_cnt, 1);
            if (p < TK_CAP) { ukey[p] = u1; uidx[p] = idx + 1; }
        }
        if (u2 >= TAU0) {
            int p = atomicAdd(&s_cnt, 1);
            if (p < TK_CAP) { ukey[p] = u2; uidx[p] = idx + 2; }
        }
        if (u3 >= TAU0) {
            int p = atomicAdd(&s_cnt, 1);
            if (p < TK_CAP) { ukey[p] = u3; uidx[p] = idx + 3; }
        }
    }
    __syncthreads();

    int cnt;
    if (s_cnt >= K_TOP && s_cnt <= TK_CAP) {
        cnt = s_cnt;
    } else {
        // fallback: full-row 2-pass scan (exact)
        unsigned* hist = ukey;
        for (int i = tid; i < TK_CAP; i += 256) hist[i] = 0u;
        __syncthreads();
#pragma unroll 4
        for (int i = 0; i < N_PAT / 256; i++) {
            unsigned u = f2ord(row[i * 256 + tid]);
            atomicAdd(&hist[u >> 20], 1u);
        }
        __syncthreads();
        const int base = 4095 - tid * 16;
        unsigned lsum = 0;
#pragma unroll
        for (int j = 0; j < 16; j++) lsum += hist[base - j];
        h2[tid] = lsum;
        __syncthreads();
        if (tid == 0) {
            unsigned run = 0;
            for (int i = 0; i < 256; i++) { unsigned c = h2[i]; h2[i] = run; run += c; }
        }
        __syncthreads();
        {
            unsigned run = h2[tid];
            if (run < (unsigned)K_TOP && run + lsum >= (unsigned)K_TOP) {
                unsigned r = run;
#pragma unroll
                for (int j = 0; j < 16; j++) {
                    unsigned c = hist[base - j];
                    if (r + c >= (unsigned)K_TOP) { s_b = base - j; s_cg = (int)r; break; }
                    r += c;
                }
            }
        }
        if (tid == 0) s_cnt = 0;
        __syncthreads();
        const unsigned floorkey = ((unsigned)s_b) << 20;
        __syncthreads();
#pragma unroll 4
        for (int i = 0; i < N_PAT / 256; i++) {
            const int idx = i * 256 + tid;
            unsigned u = f2ord(row[idx]);
            if (u >= floorkey) {
                int p = atomicAdd(&s_cnt, 1);
                if (p < 2048) { ukey[p] = u; uidx[p] = idx; }
            }
        }
        __syncthreads();
        cnt = min(s_cnt, 2048);
    }

    // exact full-key radix select
    if (tid == 0) { s_prefix = 0u; s_want = K_TOP; }
    __syncthreads();

#pragma unroll
    for (int p = 0; p < 4; p++) {
        const int sh = 24 - 8 * p;
        h2[tid] = 0u;
        __syncthreads();
        const unsigned mask_hi = (p == 0) ? 0u : ~((0x1u << (sh + 8)) - 1u);
        const unsigned pfx = s_prefix;
        for (int i = tid; i < cnt; i += 256) {
            unsigned u = ukey[i];
            if ((u & mask_hi) == pfx)
                atomicAdd(&h2[(u >> sh) & 255u], 1u);
        }
        __syncthreads();
        if (tid == 0) {
            unsigned run = 0;
            int want = s_want;
            for (int bin = 255; bin >= 0; bin--) {
                unsigned c = h2[bin];
                if (run + c >= (unsigned)want) {
                    s_prefix = pfx | ((unsigned)bin << sh);
                    s_want = want - (int)run;
                    break;
                }
                run += c;
            }
        }
        __syncthreads();
    }

    const unsigned tau = s_prefix;
    const int want_eq = s_want;

    if (tid == 0) { s_out = 0; s_ce = 0; }
    __syncthreads();

    for (int i = tid; i < cnt; i += 256) {
        unsigned u = ukey[i];
        if (u > tau) {
            int p = atomicAdd(&s_out, 1);
            if (p < K_TOP) outsel[p] = uidx[i];
        } else if (u == tau) {
            int p = atomicAdd(&s_ce, 1);
            if (p < TK_EQ) eqidx[p] = uidx[i];
        }
    }
    __syncthreads();

    if (tid == 0) {
        const int cg = min(s_out, K_TOP);
        int ce = min(s_ce, TK_EQ);
        int need = min(want_eq, ce);
        for (int s = 0; s < need; s++) {
            int best = s;
            for (int q = s + 1; q < ce; q++)
                if (eqidx[q] < eqidx[best]) best = q;
            int tmp = eqidx[s]; eqidx[s] = eqidx[best]; eqidx[best] = tmp;
            outsel[cg + s] = eqidx[s];
        }
    }
    __syncthreads();

    for (int k = 2; k <= K_TOP; k <<= 1) {
        for (int j = k >> 1; j > 0; j >>= 1) {
            if (tid < K_TOP) {
                int ixj = tid ^ j;
                if (ixj > tid) {
                    int a = outsel[tid], b = outsel[ixj];
                    bool asc = ((tid & k) == 0);
                    if (asc ? (a > b) : (a < b)) { outsel[tid] = b; outsel[ixj] = a; }
                }
            }
            __syncthreads();
        }
    }
    if (tid < K_TOP) topk[(size_t)t * K_TOP + tid] = outsel[tid];
}

// ============================================================================
// Gather halves (sorted indices -> deterministic) + combine into bf16 split.
// ============================================================================
__global__ __launch_bounds__(256)
void gather_half_kernel(const float* __restrict__ patterns,
                        const int* __restrict__ topk,
                        float* __restrict__ p0, float* __restrict__ p1)
{
    const int b = blockIdx.x;
    const int t = b >> 1;
    const int half = b & 1;
    const int tid = threadIdx.x;

    __shared__ int sidx[64];
    if (tid < 64) sidx[tid] = topk[(size_t)t * K_TOP + half * 64 + tid];
    __syncthreads();

    float a0 = 0.0f, a1 = 0.0f;
#pragma unroll 4
    for (int k = 0; k < 64; k++) {
        const float* prow = patterns + (size_t)sidx[k] * P_DIM;
        a0 += prow[tid];
        a1 += prow[tid + 256];
    }
    float* dst = (half ? p1 : p0) + (size_t)t * P_DIM;
    dst[tid] = a0;
    dst[tid + 256] = a1;
}

__global__ __launch_bounds__(256)
void combine_split_kernel(const float* __restrict__ p0,
                          const float* __restrict__ p1,
                          __nv_bfloat16* __restrict__ mh,
                          __nv_bfloat16* __restrict__ ml, int n)
{
    int i = blockIdx.x * 256 + threadIdx.x;
    if (i < n) {
        float v = (p0[i] + p1[i]) * (1.0f / K_TOP);
        __nv_bfloat16 hh = __float2bfloat16(v);
        mh[i] = hh;
        ml[i] = __float2bfloat16(v - __bfloat162float(hh));
    }
}

// ============================================================================
// Launch
// ============================================================================
extern "C" void kernel_launch(void* const* d_in, const int* in_sizes, int n_in,
                              void* d_out, int out_size)
{
    const float* x        = (const float*)d_in[0];
    const float* patterns = (const float*)d_in[1];
    const float* alpha    = (const float*)d_in[2];
    const float* enc_w    = (const float*)d_in[3];
    const float* enc_b    = (const float*)d_in[4];
    const float* dec_w    = (const float*)d_in[5];
    const float* dec_b    = (const float*)d_in[6];
    float* out = (float*)d_out;

    float *enc, *sim, *p0, *p1;
    __nv_bfloat16 *Ah, *Al, *Bh, *Bl, *xh, *xl, *ewh, *ewl, *dwh, *dwl, *mh, *ml;
    int* topk;
    cudaGetSymbolAddress((void**)&enc,  g_enc);
    cudaGetSymbolAddress((void**)&Ah,   g_Ah);
    cudaGetSymbolAddress((void**)&Al,   g_Al);
    cudaGetSymbolAddress((void**)&Bh,   g_Bh);
    cudaGetSymbolAddress((void**)&Bl,   g_Bl);
    cudaGetSymbolAddress((void**)&xh,   g_xh);
    cudaGetSymbolAddress((void**)&xl,   g_xl);
    cudaGetSymbolAddress((void**)&ewh,  g_ewh);
    cudaGetSymbolAddress((void**)&ewl,  g_ewl);
    cudaGetSymbolAddress((void**)&dwh,  g_dwh);
    cudaGetSymbolAddress((void**)&dwl,  g_dwl);
    cudaGetSymbolAddress((void**)&sim,  g_sim);
    cudaGetSymbolAddress((void**)&topk, g_topk);
    cudaGetSymbolAddress((void**)&p0,   g_p0);
    cudaGetSymbolAddress((void**)&p1,   g_p1);
    cudaGetSymbolAddress((void**)&mh,   g_mh);
    cudaGetSymbolAddress((void**)&ml,   g_ml);

    cudaFuncSetAttribute(sim_mma_kernel,
                         cudaFuncAttributeMaxDynamicSharedMemorySize, SIM_SMEM_B);
    cudaFuncSetAttribute((const void*)hmma_gemm_kernel<1, 32, 512, 1024>,
                         cudaFuncAttributeMaxDynamicSharedMemorySize, SIM_SMEM_B);
    cudaFuncSetAttribute((const void*)hmma_gemm_kernel<2, 16, 1024, 512>,
                         cudaFuncAttributeMaxDynamicSharedMemorySize, SIM_SMEM_B);

    // 0) bf16 splits of x, enc_w, dec_w (single segmented launch)
    {
        const int n0 = T_TOK * D_DIM;       // 4 Mi
        const int n1 = P_DIM * D_DIM;       // 0.5 Mi
        const int n2 = D_DIM * P_DIM;       // 0.5 Mi
        const int total = n0 + n1 + n2;
        split3_kernel<<<(total + 255) / 256, 256>>>(
            x, xh, xl, n0, enc_w, ewh, ewl, n1, dec_w, dwh, dwl, n2);
    }

    // 1) encoder GEMM (HMMA)
    {
        dim3 grid(T_TOK / 128, P_DIM / 128);
        hmma_gemm_kernel<1, 32, 512, 1024><<<grid, 256, SIM_SMEM_B>>>(
            xh, xl, ewh, ewl, enc_b, enc, nullptr, nullptr);
    }
    // 2) normalize + bf16x2 split
    rownorm_split_kernel<<<T_TOK, 256>>>(enc, Ah, Al);
    rownorm_split_kernel<<<N_PAT, 256>>>(patterns, Bh, Bl);
    // 3) sim GEMM (HMMA bf16x3, R9 mainloop)
    {
        dim3 grid(T_TOK / 128, N_PAT / 128);
        sim_mma_kernel<<<grid, 256, SIM_SMEM_B>>>(Ah, Al, Bh, Bl, sim);
    }
    // 4) exact top-128 (sorted output)
    topk_kernel<<<T_TOK, 256>>>(sim, topk);
    // 5) gather halves + combine into bf16-split mean
    gather_half_kernel<<<T_TOK * 2, 256>>>(patterns, topk, p0, p1);
    combine_split_kernel<<<(T_TOK * P_DIM + 255) / 256, 256>>>(p0, p1, mh, ml,
                                                               T_TOK * P_DIM);
    // 6) decoder GEMM + residual (HMMA)
    {
        dim3 grid(T_TOK / 128, D_DIM / 128);
        hmma_gemm_kernel<2, 16, 1024, 512><<<grid, 256, SIM_SMEM_B>>>(
            mh, ml, dwh, dwl, dec_b, out, x, alpha);
    }
}

// round 16
// speedup vs baseline: 1.0768x; 1.0258x over previous
#include <cuda_runtime.h>
#include <cuda_bf16.h>
#include <cstdint>
#include <cstddef>

// ----------------------------------------------------------------------------
//   x[T,D] -> enc = x @ enc_w^T + enc_b            (T=4096, D=1024, P=512)
//   enc_n, pat_n = L2-normalized rows (eps 1e-8)
//   sim = enc_n @ pat_n^T                          [T, N]  N=65536
//   idx = top-128(sim); mean_pat = mean(patterns[idx])
//   out = x + alpha * (mean_pat @ dec_w^T + dec_b)
//
// GEMMs: HMMA bf16x3 (AhBh + AhBl + AlBh, fp32 accum), R9 mainloop (FROZEN).
// This round: MLP fixes in the memory kernels only —
//   topk prefilter: 4 batched float4 loads/iter (output bits identical)
//   gather: float2-per-row unroll-8 (output bits identical)
//   rownorm: warp-per-row, shuffle-only reduce (ulp-level drift allowed)
// ----------------------------------------------------------------------------

#define T_TOK 4096
#define D_DIM 1024
#define P_DIM 512
#define N_PAT 65536
#define K_TOP 128

// Static scratch (no runtime allocation).
__device__ float         g_enc [(size_t)T_TOK * P_DIM];
__device__ __nv_bfloat16 g_Ah  [(size_t)T_TOK * P_DIM];
__device__ __nv_bfloat16 g_Al  [(size_t)T_TOK * P_DIM];
__device__ __nv_bfloat16 g_Bh  [(size_t)N_PAT * P_DIM];
__device__ __nv_bfloat16 g_Bl  [(size_t)N_PAT * P_DIM];
__device__ __nv_bfloat16 g_xh [(size_t)T_TOK * D_DIM];
__device__ __nv_bfloat16 g_xl [(size_t)T_TOK * D_DIM];
__device__ __nv_bfloat16 g_ewh[(size_t)P_DIM * D_DIM];
__device__ __nv_bfloat16 g_ewl[(size_t)P_DIM * D_DIM];
__device__ __nv_bfloat16 g_dwh[(size_t)D_DIM * P_DIM];
__device__ __nv_bfloat16 g_dwl[(size_t)D_DIM * P_DIM];
__device__ float         g_sim [(size_t)T_TOK * N_PAT];   // 1 GiB
__device__ int           g_topk[(size_t)T_TOK * K_TOP];
__device__ float         g_p0  [(size_t)T_TOK * P_DIM];
__device__ float         g_p1  [(size_t)T_TOK * P_DIM];
__device__ __nv_bfloat16 g_mh  [(size_t)T_TOK * P_DIM];
__device__ __nv_bfloat16 g_ml  [(size_t)T_TOK * P_DIM];

// ============================================================================
// PTX helpers — all compute_80-level (safe for compute_103 without 'a')
// ============================================================================
__device__ __forceinline__ uint32_t smem_to_u32(const void* p) {
    uint32_t a;
    asm("{ .reg .u64 t; cvta.to.shared.u64 t, %1; cvt.u32.u64 %0, t; }"
        : "=r"(a) : "l"(p));
    return a;
}

__device__ __forceinline__ void ldsm4(uint32_t& r0, uint32_t& r1,
                                      uint32_t& r2, uint32_t& r3, uint32_t a) {
    asm volatile("ldmatrix.sync.aligned.m8n8.x4.shared.b16 {%0,%1,%2,%3}, [%4];"
                 : "=r"(r0), "=r"(r1), "=r"(r2), "=r"(r3) : "r"(a));
}

__device__ __forceinline__ void mma16816(float* c,
                                         const uint32_t* a,
                                         const uint32_t* b) {
    asm volatile(
        "mma.sync.aligned.m16n8k16.row.col.f32.bf16.bf16.f32 "
        "{%0,%1,%2,%3}, {%4,%5,%6,%7}, {%8,%9}, {%0,%1,%2,%3};"
        : "+f"(c[0]), "+f"(c[1]), "+f"(c[2]), "+f"(c[3])
        : "r"(a[0]), "r"(a[1]), "r"(a[2]), "r"(a[3]), "r"(b[0]), "r"(b[1]));
}

#define CP_ASYNC16(dst_u32, src_ptr) \
    asm volatile("cp.async.cg.shared.global [%0], [%1], 16;" \
                 :: "r"(dst_u32), "l"(src_ptr))
#define CP_COMMIT() asm volatile("cp.async.commit_group;" ::: "memory")
#define CP_WAIT(n)  asm volatile("cp.async.wait_group %0;" :: "n"(n) : "memory")

__device__ __forceinline__ unsigned f2ord(float f) {
    unsigned x = __float_as_uint(f);
    return x ^ ((x & 0x80000000u) ? 0xFFFFFFFFu : 0x80000000u);
}

// ============================================================================
// Shared tile-copy for all HMMA GEMMs (4 tensors, double buffer).
// SMEM chunk: [128 rows x 32 k] bf16; 16B chunk (row,c16) at row*80 + c16*16.
// ============================================================================
#define SIM_TILE_B   10240
#define SIM_BUF_B    40960
#define SIM_SMEM_B   81920

__device__ __forceinline__ void hmma_cp_chunk(
    uint32_t sbase,
    const __nv_bfloat16* __restrict__ Ah, const __nv_bfloat16* __restrict__ Al,
    const __nv_bfloat16* __restrict__ Bh, const __nv_bfloat16* __restrict__ Bl,
    int m0, int n0, int c, int buf, int tid, int kdim)
{
    const int kofs = c * 32;
    const uint32_t dbase = sbase + (uint32_t)buf * SIM_BUF_B;
#pragma unroll
    for (int t = 0; t < 4; t++) {
        const __nv_bfloat16* src = (t == 0) ? Ah : (t == 1) ? Al : (t == 2) ? Bh : Bl;
        const int rbase = (t < 2) ? m0 : n0;
#pragma unroll
        for (int i = 0; i < 2; i++) {
            int lin = i * 256 + tid;      // 512 chunks of 16B per tile
            int row = lin >> 2;           // 0..127
            int c16 = lin & 3;            // 0..3
            const void* g = src + (size_t)(rbase + row) * kdim + kofs + c16 * 8;
            uint32_t d = dbase + (uint32_t)t * SIM_TILE_B
                       + (uint32_t)(row * 80 + c16 * 16);
            CP_ASYNC16(d, g);
        }
    }
    CP_COMMIT();
}

// ============================================================================
// Shared mainloop body (compute one 32-wide K-chunk from SMEM buf).
// ============================================================================
__device__ __forceinline__ void hmma_compute_chunk(
    uint32_t bufbase, int lane, int warp_m, int warp_n, float acc[2][8][4])
{
    const uint32_t ab  = bufbase;
    const uint32_t alb = bufbase + SIM_TILE_B;
    const uint32_t bhb = bufbase + 2 * SIM_TILE_B;
    const uint32_t blb = bufbase + 3 * SIM_TILE_B;

#pragma unroll
    for (int ks = 0; ks < 2; ks++) {
        uint32_t fah[2][4], fal[2][4];
        {
            const int arow = warp_m * 32 + (lane & 15);
            const int ac16 = ks * 2 + (lane >> 4);
#pragma unroll
            for (int mi = 0; mi < 2; mi++) {
                uint32_t off = (uint32_t)((arow + mi * 16) * 80 + ac16 * 16);
                ldsm4(fah[mi][0], fah[mi][1], fah[mi][2], fah[mi][3], ab + off);
                ldsm4(fal[mi][0], fal[mi][1], fal[mi][2], fal[mi][3], alb + off);
            }
        }
        uint32_t fbh[8][2], fbl[8][2];
        {
            const int g = lane >> 3;
            const int brow = warp_n * 64 + (g >> 1) * 8 + (lane & 7);
            const int bc16 = ks * 2 + (g & 1);
#pragma unroll
            for (int np = 0; np < 4; np++) {
                uint32_t off = (uint32_t)((brow + np * 16) * 80 + bc16 * 16);
                uint32_t r0, r1, r2, r3;
                ldsm4(r0, r1, r2, r3, bhb + off);
                fbh[np * 2][0] = r0; fbh[np * 2][1] = r1;
                fbh[np * 2 + 1][0] = r2; fbh[np * 2 + 1][1] = r3;
                ldsm4(r0, r1, r2, r3, blb + off);
                fbl[np * 2][0] = r0; fbl[np * 2][1] = r1;
                fbl[np * 2 + 1][0] = r2; fbl[np * 2 + 1][1] = r3;
            }
        }
#pragma unroll
        for (int mi = 0; mi < 2; mi++)
#pragma unroll
            for (int ni = 0; ni < 8; ni++) {
                mma16816(acc[mi][ni], fah[mi], fbh[ni]);
                mma16816(acc[mi][ni], fah[mi], fbl[ni]);
                mma16816(acc[mi][ni], fal[mi], fbh[ni]);
            }
    }
}

// ============================================================================
// sim GEMM — R9 structure (FROZEN): issue cp(c+1) -> CP_WAIT(1) -> barrier ->
// compute(c) -> barrier.
// ============================================================================
__global__ __launch_bounds__(256)
void sim_mma_kernel(const __nv_bfloat16* __restrict__ Ah,
                    const __nv_bfloat16* __restrict__ Al,
                    const __nv_bfloat16* __restrict__ Bh,
                    const __nv_bfloat16* __restrict__ Bl,
                    float* __restrict__ sim)
{
    extern __shared__ char smem[];
    const uint32_t sbase = smem_to_u32(smem);
    const int tid = threadIdx.x;
    const int wid = tid >> 5;
    const int lane = tid & 31;
    const int m0 = blockIdx.x * 128;   // x fastest over M -> B tile shared in wave
    const int n0 = blockIdx.y * 128;
    const int warp_m = wid >> 1;
    const int warp_n = wid & 1;

    float acc[2][8][4];
#pragma unroll
    for (int mi = 0; mi < 2; mi++)
#pragma unroll
        for (int ni = 0; ni < 8; ni++)
#pragma unroll
            for (int q = 0; q < 4; q++) acc[mi][ni][q] = 0.0f;

    hmma_cp_chunk(sbase, Ah, Al, Bh, Bl, m0, n0, 0, 0, tid, P_DIM);

    for (int c = 0; c < 16; c++) {
        if (c + 1 < 16) {
            hmma_cp_chunk(sbase, Ah, Al, Bh, Bl, m0, n0, c + 1, (c + 1) & 1,
                          tid, P_DIM);
            CP_WAIT(1);
        } else {
            CP_WAIT(0);
        }
        __syncthreads();
        hmma_compute_chunk(sbase + (uint32_t)(c & 1) * SIM_BUF_B,
                           lane, warp_m, warp_n, acc);
        __syncthreads();
    }

    const int row = m0 + warp_m * 32 + (lane >> 2);
    const int colb = n0 + warp_n * 64 + (lane & 3) * 2;
#pragma unroll
    for (int mi = 0; mi < 2; mi++)
#pragma unroll
        for (int ni = 0; ni < 8; ni++) {
            float2 v01 = make_float2(acc[mi][ni][0], acc[mi][ni][1]);
            float2 v23 = make_float2(acc[mi][ni][2], acc[mi][ni][3]);
            *reinterpret_cast<float2*>(
                &sim[(size_t)(row + mi * 16) * N_PAT + colb + ni * 8]) = v01;
            *reinterpret_cast<float2*>(
                &sim[(size_t)(row + mi * 16 + 8) * N_PAT + colb + ni * 8]) = v23;
        }
}

// ============================================================================
// Generic HMMA GEMM for enc/dec — same R9 loop structure.
// EPI 1: C = acc + bias[n];  EPI 2: C = resid + alpha[0]*(acc + bias[n])
// ============================================================================
template <int EPI, int KCHUNKS, int NOUT, int KDIM>
__global__ __launch_bounds__(256)
void hmma_gemm_kernel(const __nv_bfloat16* __restrict__ Ah,
                      const __nv_bfloat16* __restrict__ Al,
                      const __nv_bfloat16* __restrict__ Bh,
                      const __nv_bfloat16* __restrict__ Bl,
                      const float* __restrict__ bias,
                      float* __restrict__ C,
                      const float* __restrict__ resid,
                      const float* __restrict__ alpha)
{
    extern __shared__ char smem[];
    const uint32_t sbase = smem_to_u32(smem);
    const int tid = threadIdx.x;
    const int wid = tid >> 5;
    const int lane = tid & 31;
    const int m0 = blockIdx.x * 128;
    const int n0 = blockIdx.y * 128;
    const int warp_m = wid >> 1;
    const int warp_n = wid & 1;

    float acc[2][8][4];
#pragma unroll
    for (int mi = 0; mi < 2; mi++)
#pragma unroll
        for (int ni = 0; ni < 8; ni++)
#pragma unroll
            for (int q = 0; q < 4; q++) acc[mi][ni][q] = 0.0f;

    hmma_cp_chunk(sbase, Ah, Al, Bh, Bl, m0, n0, 0, 0, tid, KDIM);

    for (int c = 0; c < KCHUNKS; c++) {
        if (c + 1 < KCHUNKS) {
            hmma_cp_chunk(sbase, Ah, Al, Bh, Bl, m0, n0, c + 1, (c + 1) & 1,
                          tid, KDIM);
            CP_WAIT(1);
        } else {
            CP_WAIT(0);
        }
        __syncthreads();
        hmma_compute_chunk(sbase + (uint32_t)(c & 1) * SIM_BUF_B,
                           lane, warp_m, warp_n, acc);
        __syncthreads();
    }

    const float a_val = (EPI == 2) ? alpha[0] : 0.0f;
    const int row = m0 + warp_m * 32 + (lane >> 2);
    const int colb = n0 + warp_n * 64 + (lane & 3) * 2;
#pragma unroll
    for (int mi = 0; mi < 2; mi++)
#pragma unroll
        for (int ni = 0; ni < 8; ni++) {
            const int c0 = colb + ni * 8;
            const float b0 = bias[c0], b1 = bias[c0 + 1];
#pragma unroll
            for (int rr = 0; rr < 2; rr++) {
                const int r = row + mi * 16 + rr * 8;
                const size_t off = (size_t)r * NOUT + c0;
                float v0 = acc[mi][ni][rr * 2 + 0] + b0;
                float v1 = acc[mi][ni][rr * 2 + 1] + b1;
                if (EPI == 2) {
                    v0 = resid[off] + a_val * v0;
                    v1 = resid[off + 1] + a_val * v1;
                }
                *reinterpret_cast<float2*>(&C[off]) = make_float2(v0, v1);
            }
        }
}

// ============================================================================
// fp32 -> bf16 high/low split, three segments in ONE launch.
// ============================================================================
__global__ __launch_bounds__(256)
void split3_kernel(const float* __restrict__ s0, __nv_bfloat16* __restrict__ h0,
                   __nv_bfloat16* __restrict__ l0, int n0,
                   const float* __restrict__ s1, __nv_bfloat16* __restrict__ h1,
                   __nv_bfloat16* __restrict__ l1, int n1,
                   const float* __restrict__ s2, __nv_bfloat16* __restrict__ h2,
                   __nv_bfloat16* __restrict__ l2, int n2)
{
    int i = blockIdx.x * 256 + threadIdx.x;
    const float* src;
    __nv_bfloat16 *dh, *dl;
    int j;
    if (i < n0)           { src = s0; dh = h0; dl = l0; j = i; }
    else if (i < n0 + n1) { src = s1; dh = h1; dl = l1; j = i - n0; }
    else if (i < n0 + n1 + n2) { src = s2; dh = h2; dl = l2; j = i - n0 - n1; }
    else return;
    float v = src[j];
    __nv_bfloat16 hh = __float2bfloat16(v);
    dh[j] = hh;
    dl[j] = __float2bfloat16(v - __bfloat162float(hh));
}

// ============================================================================
// Row L2-normalize + bf16x2 split — WARP-PER-ROW (8 rows/block).
// Lane owns cols lane + 32*j (j=0..15): 16 coalesced loads, full MLP,
// shuffle-only reduction (no block barriers).
// ============================================================================
__global__ __launch_bounds__(256)
void rownorm_split_kernel(const float* __restrict__ in,
                          __nv_bfloat16* __restrict__ oh,
                          __nv_bfloat16* __restrict__ ol)
{
    const int warp = threadIdx.x >> 5;
    const int lane = threadIdx.x & 31;
    const int r = blockIdx.x * 8 + warp;
    const float* row = in + (size_t)r * P_DIM;

    float v[16];
#pragma unroll
    for (int j = 0; j < 16; j++) v[j] = row[lane + 32 * j];

    float ss = 0.0f;
#pragma unroll
    for (int j = 0; j < 16; j++) ss = fmaf(v[j], v[j], ss);
#pragma unroll
    for (int o = 16; o > 0; o >>= 1) ss += __shfl_xor_sync(0xFFFFFFFFu, ss, o);

    const float inv = 1.0f / fmaxf(sqrtf(ss), 1e-8f);

    __nv_bfloat16* ohr = oh + (size_t)r * P_DIM;
    __nv_bfloat16* olr = ol + (size_t)r * P_DIM;
#pragma unroll
    for (int j = 0; j < 16; j++) {
        float n = v[j] * inv;
        __nv_bfloat16 h = __float2bfloat16(n);
        ohr[lane + 32 * j] = h;
        olr[lane + 32 * j] = __float2bfloat16(n - __bfloat162float(h));
    }
}

// ============================================================================
// Exact top-128 per token (1-pass >=2sigma prefilter + exact fallback).
// Prefilter batches 4 independent float4 loads per iteration (MLP=4).
// Output set identical to R9 (order-independent select + sorted output).
// ============================================================================
#define TK_CAP 4096
#define TK_EQ  64

__global__ __launch_bounds__(256)
void topk_kernel(const float* __restrict__ sim, int* __restrict__ topk)
{
    const int t = blockIdx.x;
    const int tid = threadIdx.x;
    const float* row = sim + (size_t)t * N_PAT;

    __shared__ unsigned ukey[TK_CAP];   // fallback aliases this as hist[4096]
    __shared__ int      uidx[TK_CAP];
    __shared__ unsigned h2[256];
    __shared__ unsigned s_prefix;
    __shared__ int s_want, s_out, s_ce, s_cnt, s_b, s_cg;
    __shared__ int eqidx[TK_EQ];
    __shared__ int outsel[K_TOP];

    const unsigned TAU0 = f2ord(0.0883883476f);   // 2/sqrt(512)

    if (tid == 0) s_cnt = 0;
    __syncthreads();

    // 16 outer iterations x 4 batched float4 loads (independent -> MLP=4)
    for (int i = 0; i < N_PAT / 4096; i++) {
        float4 v[4];
#pragma unroll
        for (int j = 0; j < 4; j++)
            v[j] = *reinterpret_cast<const float4*>(
                &row[((i * 4 + j) * 256 + tid) * 4]);
#pragma unroll
        for (int j = 0; j < 4; j++) {
            const int idx = ((i * 4 + j) * 256 + tid) * 4;
            unsigned u0 = f2ord(v[j].x), u1 = f2ord(v[j].y);
            unsigned u2 = f2ord(v[j].z), u3 = f2ord(v[j].w);
            if (u0 >= TAU0) {
                int p = atomicAdd(&s_cnt, 1);
                if (p < TK_CAP) { ukey[p] = u0; uidx[p] = idx; }
            }
            if (u1 >= TAU0) {
                int p = atomicAdd(&s_cnt, 1);
                if (p < TK_CAP) { ukey[p] = u1; uidx[p] = idx + 1; }
            }
            if (u2 >= TAU0) {
                int p = atomicAdd(&s_cnt, 1);
                if (p < TK_CAP) { ukey[p] = u2; uidx[p] = idx + 2; }
            }
            if (u3 >= TAU0) {
                int p = atomicAdd(&s_cnt, 1);
                if (p < TK_CAP) { ukey[p] = u3; uidx[p] = idx + 3; }
            }
        }
    }
    __syncthreads();

    int cnt;
    if (s_cnt >= K_TOP && s_cnt <= TK_CAP) {
        cnt = s_cnt;
    } else {
        // fallback: full-row 2-pass scan (exact)
        unsigned* hist = ukey;
        for (int i = tid; i < TK_CAP; i += 256) hist[i] = 0u;
        __syncthreads();
#pragma unroll 4
        for (int i = 0; i < N_PAT / 256; i++) {
            unsigned u = f2ord(row[i * 256 + tid]);
            atomicAdd(&hist[u >> 20], 1u);
        }
        __syncthreads();
        const int base = 4095 - tid * 16;
        unsigned lsum = 0;
#pragma unroll
        for (int j = 0; j < 16; j++) lsum += hist[base - j];
        h2[tid] = lsum;
        __syncthreads();
        if (tid == 0) {
            unsigned run = 0;
            for (int i = 0; i < 256; i++) { unsigned c = h2[i]; h2[i] = run; run += c; }
        }
        __syncthreads();
        {
            unsigned run = h2[tid];
            if (run < (unsigned)K_TOP && run + lsum >= (unsigned)K_TOP) {
                unsigned r = run;
#pragma unroll
                for (int j = 0; j < 16; j++) {
                    unsigned c = hist[base - j];
                    if (r + c >= (unsigned)K_TOP) { s_b = base - j; s_cg = (int)r; break; }
                    r += c;
                }
            }
        }
        if (tid == 0) s_cnt = 0;
        __syncthreads();
        const unsigned floorkey = ((unsigned)s_b) << 20;
        __syncthreads();
#pragma unroll 4
        for (int i = 0; i < N_PAT / 256; i++) {
            const int idx = i * 256 + tid;
            unsigned u = f2ord(row[idx]);
            if (u >= floorkey) {
                int p = atomicAdd(&s_cnt, 1);
                if (p < 2048) { ukey[p] = u; uidx[p] = idx; }
            }
        }
        __syncthreads();
        cnt = min(s_cnt, 2048);
    }

    // exact full-key radix select
    if (tid == 0) { s_prefix = 0u; s_want = K_TOP; }
    __syncthreads();

#pragma unroll
    for (int p = 0; p < 4; p++) {
        const int sh = 24 - 8 * p;
        h2[tid] = 0u;
        __syncthreads();
        const unsigned mask_hi = (p == 0) ? 0u : ~((0x1u << (sh + 8)) - 1u);
        const unsigned pfx = s_prefix;
        for (int i = tid; i < cnt; i += 256) {
            unsigned u = ukey[i];
            if ((u & mask_hi) == pfx)
                atomicAdd(&h2[(u >> sh) & 255u], 1u);
        }
        __syncthreads();
        if (tid == 0) {
            unsigned run = 0;
            int want = s_want;
            for (int bin = 255; bin >= 0; bin--) {
                unsigned c = h2[bin];
                if (run + c >= (unsigned)want) {
                    s_prefix = pfx | ((unsigned)bin << sh);
                    s_want = want - (int)run;
                    break;
                }
                run += c;
            }
        }
        __syncthreads();
    }

    const unsigned tau = s_prefix;
    const int want_eq = s_want;

    if (tid == 0) { s_out = 0; s_ce = 0; }
    __syncthreads();

    for (int i = tid; i < cnt; i += 256) {
        unsigned u = ukey[i];
        if (u > tau) {
            int p = atomicAdd(&s_out, 1);
            if (p < K_TOP) outsel[p] = uidx[i];
        } else if (u == tau) {
            int p = atomicAdd(&s_ce, 1);
            if (p < TK_EQ) eqidx[p] = uidx[i];
        }
    }
    __syncthreads();

    if (tid == 0) {
        const int cg = min(s_out, K_TOP);
        int ce = min(s_ce, TK_EQ);
        int need = min(want_eq, ce);
        for (int s = 0; s < need; s++) {
            int best = s;
            for (int q = s + 1; q < ce; q++)
                if (eqidx[q] < eqidx[best]) best = q;
            int tmp = eqidx[s]; eqidx[s] = eqidx[best]; eqidx[best] = tmp;
            outsel[cg + s] = eqidx[s];
        }
    }
    __syncthreads();

    for (int k = 2; k <= K_TOP; k <<= 1) {
        for (int j = k >> 1; j > 0; j >>= 1) {
            if (tid < K_TOP) {
                int ixj = tid ^ j;
                if (ixj > tid) {
                    int a = outsel[tid], b = outsel[ixj];
                    bool asc = ((tid & k) == 0);
                    if (asc ? (a > b) : (a < b)) { outsel[tid] = b; outsel[ixj] = a; }
                }
            }
            __syncthreads();
        }
    }
    if (tid < K_TOP) topk[(size_t)t * K_TOP + tid] = outsel[tid];
}

// ============================================================================
// Gather halves — float2 per thread per row, unroll 8 (MLP=8).
// Per-column summation order unchanged -> bits identical to R9.
// ============================================================================
__global__ __launch_bounds__(256)
void gather_half_kernel(const float* __restrict__ patterns,
                        const int* __restrict__ topk,
                        float* __restrict__ p0, float* __restrict__ p1)
{
    const int b = blockIdx.x;
    const int t = b >> 1;
    const int half = b & 1;
    const int tid = threadIdx.x;
    const int c2 = tid * 2;

    __shared__ int sidx[64];
    if (tid < 64) sidx[tid] = topk[(size_t)t * K_TOP + half * 64 + tid];
    __syncthreads();

    float a0 = 0.0f, a1 = 0.0f;
#pragma unroll 8
    for (int k = 0; k < 64; k++) {
        float2 v = *reinterpret_cast<const float2*>(
            &patterns[(size_t)sidx[k] * P_DIM + c2]);
        a0 += v.x;
        a1 += v.y;
    }
    float* dst = (half ? p1 : p0) + (size_t)t * P_DIM;
    *reinterpret_cast<float2*>(&dst[c2]) = make_float2(a0, a1);
}

__global__ __launch_bounds__(256)
void combine_split_kernel(const float* __restrict__ p0,
                          const float* __restrict__ p1,
                          __nv_bfloat16* __restrict__ mh,
                          __nv_bfloat16* __restrict__ ml, int n)
{
    int i = blockIdx.x * 256 + threadIdx.x;
    if (i < n) {
        float v = (p0[i] + p1[i]) * (1.0f / K_TOP);
        __nv_bfloat16 hh = __float2bfloat16(v);
        mh[i] = hh;
        ml[i] = __float2bfloat16(v - __bfloat162float(hh));
    }
}

// ============================================================================
// Launch
// ============================================================================
extern "C" void kernel_launch(void* const* d_in, const int* in_sizes, int n_in,
                              void* d_out, int out_size)
{
    const float* x        = (const float*)d_in[0];
    const float* patterns = (const float*)d_in[1];
    const float* alpha    = (const float*)d_in[2];
    const float* enc_w    = (const float*)d_in[3];
    const float* enc_b    = (const float*)d_in[4];
    const float* dec_w    = (const float*)d_in[5];
    const float* dec_b    = (const float*)d_in[6];
    float* out = (float*)d_out;

    float *enc, *sim, *p0, *p1;
    __nv_bfloat16 *Ah, *Al, *Bh, *Bl, *xh, *xl, *ewh, *ewl, *dwh, *dwl, *mh, *ml;
    int* topk;
    cudaGetSymbolAddress((void**)&enc,  g_enc);
    cudaGetSymbolAddress((void**)&Ah,   g_Ah);
    cudaGetSymbolAddress((void**)&Al,   g_Al);
    cudaGetSymbolAddress((void**)&Bh,   g_Bh);
    cudaGetSymbolAddress((void**)&Bl,   g_Bl);
    cudaGetSymbolAddress((void**)&xh,   g_xh);
    cudaGetSymbolAddress((void**)&xl,   g_xl);
    cudaGetSymbolAddress((void**)&ewh,  g_ewh);
    cudaGetSymbolAddress((void**)&ewl,  g_ewl);
    cudaGetSymbolAddress((void**)&dwh,  g_dwh);
    cudaGetSymbolAddress((void**)&dwl,  g_dwl);
    cudaGetSymbolAddress((void**)&sim,  g_sim);
    cudaGetSymbolAddress((void**)&topk, g_topk);
    cudaGetSymbolAddress((void**)&p0,   g_p0);
    cudaGetSymbolAddress((void**)&p1,   g_p1);
    cudaGetSymbolAddress((void**)&mh,   g_mh);
    cudaGetSymbolAddress((void**)&ml,   g_ml);

    cudaFuncSetAttribute(sim_mma_kernel,
                         cudaFuncAttributeMaxDynamicSharedMemorySize, SIM_SMEM_B);
    cudaFuncSetAttribute((const void*)hmma_gemm_kernel<1, 32, 512, 1024>,
                         cudaFuncAttributeMaxDynamicSharedMemorySize, SIM_SMEM_B);
    cudaFuncSetAttribute((const void*)hmma_gemm_kernel<2, 16, 1024, 512>,
                         cudaFuncAttributeMaxDynamicSharedMemorySize, SIM_SMEM_B);

    // 0) bf16 splits of x, enc_w, dec_w (single segmented launch)
    {
        const int n0 = T_TOK * D_DIM;
        const int n1 = P_DIM * D_DIM;
        const int n2 = D_DIM * P_DIM;
        const int total = n0 + n1 + n2;
        split3_kernel<<<(total + 255) / 256, 256>>>(
            x, xh, xl, n0, enc_w, ewh, ewl, n1, dec_w, dwh, dwl, n2);
    }

    // 1) encoder GEMM (HMMA)
    {
        dim3 grid(T_TOK / 128, P_DIM / 128);
        hmma_gemm_kernel<1, 32, 512, 1024><<<grid, 256, SIM_SMEM_B>>>(
            xh, xl, ewh, ewl, enc_b, enc, nullptr, nullptr);
    }
    // 2) normalize + bf16x2 split (warp-per-row)
    rownorm_split_kernel<<<T_TOK / 8, 256>>>(enc, Ah, Al);
    rownorm_split_kernel<<<N_PAT / 8, 256>>>(patterns, Bh, Bl);
    // 3) sim GEMM (HMMA bf16x3, R9 mainloop)
    {
        dim3 grid(T_TOK / 128, N_PAT / 128);
        sim_mma_kernel<<<grid, 256, SIM_SMEM_B>>>(Ah, Al, Bh, Bl, sim);
    }
    // 4) exact top-128 (sorted output)
    topk_kernel<<<T_TOK, 256>>>(sim, topk);
    // 5) gather halves + combine into bf16-split mean
    gather_half_kernel<<<T_TOK * 2, 256>>>(patterns, topk, p0, p1);
    combine_split_kernel<<<(T_TOK * P_DIM + 255) / 256, 256>>>(p0, p1, mh, ml,
                                                               T_TOK * P_DIM);
    // 6) decoder GEMM + residual (HMMA)
    {
        dim3 grid(T_TOK / 128, D_DIM / 128);
        hmma_gemm_kernel<2, 16, 1024, 512><<<grid, 256, SIM_SMEM_B>>>(
            mh, ml, dwh, dwl, dec_b, out, x, alpha);
    }
}